// round 1
// baseline (speedup 1.0000x reference)
#include <cuda_runtime.h>
#include <math.h>
#include <stdint.h>

#define S_   2048
#define D_   2048
#define H_   16
#define DH_  128
#define E_   8
#define FF_  768
#define SFF_ 4096
#define EPS_ 1e-6f

// ---------------- scratch (device globals; no allocations allowed) ----------
__device__ float g_x[S_*D_];
__device__ float g_q[S_*D_];
__device__ float g_k[S_*D_];
__device__ float g_v[S_*D_];
__device__ float g_gl[S_*D_];
__device__ float g_scores[(size_t)H_*S_*S_];   // 256 MB
__device__ float g_ctx[S_*D_];
__device__ float g_hbuf[S_*D_];
__device__ float g_y[S_*D_];
__device__ float g_sg[S_*SFF_];
__device__ float g_su[S_*SFF_];
__device__ float g_shout[S_*D_];
__device__ float g_gsig[S_];
__device__ int   g_eidx[S_*2];
__device__ float g_ew[S_*2];
__device__ int   g_cnt[E_];
__device__ int   g_off[E_+1];
__device__ int   g_fill[E_];
__device__ int   g_perm[S_*2];     // slot -> token
__device__ int   g_slot[S_*2];     // token*2+k -> slot
__device__ float g_mact[(size_t)S_*2*FF_];   // silu(g)*u per slot
__device__ float g_eo[(size_t)S_*2*D_];      // expert output per slot

// ---------------- generic tiled fp32 GEMM ----------------------------------
// C = alpha * A @ B(^T) + addend ; batched over blockIdx.z via element strides.
#define BM 64
#define BN 64
#define BK 16

template<int TB>
__global__ void gemm_f32(const float* __restrict__ A, int lda, long long sA,
                         const float* __restrict__ B, int ldb, long long sB,
                         float* __restrict__ C, int ldc, long long sC,
                         int M, int N, int K, float alpha,
                         const float* __restrict__ addend, int ldadd, long long sAdd)
{
    A += (long long)blockIdx.z * sA;
    B += (long long)blockIdx.z * sB;
    C += (long long)blockIdx.z * sC;
    if (addend) addend += (long long)blockIdx.z * sAdd;

    __shared__ float As[BK][BM+1];
    __shared__ float Bs[BK][BN+1];
    int tid = threadIdx.x;
    int tx = tid & 15, ty = tid >> 4;
    int row0 = blockIdx.y * BM;
    int col0 = blockIdx.x * BN;
    float acc[4][4] = {};

    for (int k0 = 0; k0 < K; k0 += BK) {
        #pragma unroll
        for (int i = 0; i < 4; i++) {
            int idx = tid + i*256;
            int m = idx >> 4, kk = idx & 15;
            int gr = row0 + m, gk = k0 + kk;
            As[kk][m] = (gr < M && gk < K) ? A[(long long)gr*lda + gk] : 0.f;
        }
        #pragma unroll
        for (int i = 0; i < 4; i++) {
            int idx = tid + i*256;
            if (TB) {
                int n = idx >> 4, kk = idx & 15;
                int gn = col0 + n, gk = k0 + kk;
                Bs[kk][n] = (gn < N && gk < K) ? B[(long long)gn*ldb + gk] : 0.f;
            } else {
                int kk = idx >> 6, n = idx & 63;
                int gn = col0 + n, gk = k0 + kk;
                Bs[kk][n] = (gn < N && gk < K) ? B[(long long)gk*ldb + gn] : 0.f;
            }
        }
        __syncthreads();
        #pragma unroll
        for (int kk = 0; kk < BK; kk++) {
            float a[4], b[4];
            #pragma unroll
            for (int i = 0; i < 4; i++) a[i] = As[kk][ty*4+i];
            #pragma unroll
            for (int j = 0; j < 4; j++) b[j] = Bs[kk][tx*4+j];
            #pragma unroll
            for (int i = 0; i < 4; i++)
                #pragma unroll
                for (int j = 0; j < 4; j++)
                    acc[i][j] = fmaf(a[i], b[j], acc[i][j]);
        }
        __syncthreads();
    }
    #pragma unroll
    for (int i = 0; i < 4; i++) {
        int gr = row0 + ty*4 + i;
        if (gr >= M) continue;
        #pragma unroll
        for (int j = 0; j < 4; j++) {
            int gn = col0 + tx*4 + j;
            if (gn >= N) continue;
            float v = alpha * acc[i][j];
            if (addend) v += addend[(long long)gr*ldadd + gn];
            C[(long long)gr*ldc + gn] = v;
        }
    }
}

// ---------------- elementwise / reduction kernels ---------------------------
__global__ void reset_k()
{
    int i = threadIdx.x;
    if (i < E_) g_cnt[i] = 0;
}

__global__ void rmsnorm_k(const float* __restrict__ in, const float* __restrict__ w,
                          float* __restrict__ outp)
{
    int s = blockIdx.x;
    const float* x = in + (size_t)s * D_;
    float* o = outp + (size_t)s * D_;
    float ss = 0.f;
    for (int d = threadIdx.x; d < D_; d += 256) { float v = x[d]; ss += v*v; }
    __shared__ float red[256];
    red[threadIdx.x] = ss; __syncthreads();
    for (int st = 128; st > 0; st >>= 1) {
        if (threadIdx.x < st) red[threadIdx.x] += red[threadIdx.x+st];
        __syncthreads();
    }
    float r = rsqrtf(red[0]/(float)D_ + EPS_);
    for (int d = threadIdx.x; d < D_; d += 256) o[d] = x[d]*r*(1.f + w[d]);
}

__global__ void rope_k(float* __restrict__ q, float* __restrict__ k,
                       const float* __restrict__ cosp, const float* __restrict__ sinp)
{
    int idx = blockIdx.x*blockDim.x + threadIdx.x;   // over S*H*64
    if (idx >= S_*H_*64) return;
    int d = idx & 63;
    int h = (idx >> 6) & 15;
    int s = idx >> 10;
    float c1 = cosp[s*DH_ + d],      s1 = sinp[s*DH_ + d];
    float c2 = cosp[s*DH_ + d + 64], s2 = sinp[s*DH_ + d + 64];
    size_t base = (size_t)s*D_ + h*DH_ + d;
    float q1 = q[base], q2 = q[base+64];
    q[base]    = q1*c1 - q2*s1;
    q[base+64] = q2*c2 + q1*s2;
    float k1 = k[base], k2 = k[base+64];
    k[base]    = k1*c1 - k2*s1;
    k[base+64] = k2*c2 + k1*s2;
}

__global__ void softmax_k(float* __restrict__ data, int ncols)
{
    size_t row = blockIdx.x;
    float* p = data + row * (size_t)ncols;
    __shared__ float red[256];
    float m = -1e30f;
    for (int c = threadIdx.x; c < ncols; c += 256) m = fmaxf(m, p[c]);
    red[threadIdx.x] = m; __syncthreads();
    for (int st = 128; st > 0; st >>= 1) {
        if (threadIdx.x < st) red[threadIdx.x] = fmaxf(red[threadIdx.x], red[threadIdx.x+st]);
        __syncthreads();
    }
    m = red[0]; __syncthreads();
    float s = 0.f;
    for (int c = threadIdx.x; c < ncols; c += 256) { float e = expf(p[c]-m); p[c] = e; s += e; }
    red[threadIdx.x] = s; __syncthreads();
    for (int st = 128; st > 0; st >>= 1) {
        if (threadIdx.x < st) red[threadIdx.x] += red[threadIdx.x+st];
        __syncthreads();
    }
    float inv = 1.f / red[0];
    for (int c = threadIdx.x; c < ncols; c += 256) p[c] *= inv;
}

__global__ void sigmul_k(float* __restrict__ ctx, const float* __restrict__ gl)
{
    int i = blockIdx.x*blockDim.x + threadIdx.x;
    if (i >= S_*D_) return;
    ctx[i] *= 1.f / (1.f + expf(-gl[i]));
}

__global__ void router_k(const float* __restrict__ Y, const float* __restrict__ Rw)
{
    int t = blockIdx.x;
    int tid = threadIdx.x;
    float part[E_] = {};
    for (int d = tid; d < D_; d += 256) {
        float v = Y[(size_t)t*D_ + d];
        #pragma unroll
        for (int e = 0; e < E_; e++) part[e] += v * Rw[d*E_ + e];
    }
    __shared__ float red[256];
    __shared__ float logits[E_];
    for (int e = 0; e < E_; e++) {
        red[tid] = part[e]; __syncthreads();
        for (int st = 128; st > 0; st >>= 1) {
            if (tid < st) red[tid] += red[tid+st];
            __syncthreads();
        }
        if (tid == 0) logits[e] = red[0];
        __syncthreads();
    }
    if (tid == 0) {
        float m = -1e30f;
        for (int e = 0; e < E_; e++) m = fmaxf(m, logits[e]);
        float p[E_], s = 0.f;
        for (int e = 0; e < E_; e++) { p[e] = expf(logits[e]-m); s += p[e]; }
        for (int e = 0; e < E_; e++) p[e] /= s;
        int i0 = 0;
        for (int e = 1; e < E_; e++) if (p[e] > p[i0]) i0 = e;
        int i1 = (i0 == 0) ? 1 : 0;
        for (int e = 0; e < E_; e++) if (e != i0 && p[e] > p[i1]) i1 = e;
        float sum = p[i0] + p[i1];
        g_eidx[t*2]   = i0; g_eidx[t*2+1] = i1;
        g_ew[t*2]     = p[i0]/sum;
        g_ew[t*2+1]   = p[i1]/sum;
        atomicAdd(&g_cnt[i0], 1);
        atomicAdd(&g_cnt[i1], 1);
    }
}

__global__ void offsets_k()
{
    if (threadIdx.x == 0 && blockIdx.x == 0) {
        int acc = 0;
        for (int e = 0; e < E_; e++) { g_off[e] = acc; g_fill[e] = acc; acc += g_cnt[e]; }
        g_off[E_] = acc;
    }
}

__global__ void scatter_k()
{
    int t = blockIdx.x*blockDim.x + threadIdx.x;
    if (t >= S_) return;
    #pragma unroll
    for (int k = 0; k < 2; k++) {
        int e = g_eidx[t*2+k];
        int pos = atomicAdd(&g_fill[e], 1);
        g_perm[pos] = t;
        g_slot[t*2+k] = pos;
    }
}

// MoE gate+up GEMM with row gather, fused silu(g)*u epilogue.
__global__ void moe_gateup_k(const float* __restrict__ Y,
                             const float* __restrict__ Wg,
                             const float* __restrict__ Wu)
{
    int e = blockIdx.z;
    int cnt = g_cnt[e];
    int row0 = blockIdx.y * BM;
    if (row0 >= cnt) return;
    int seg = g_off[e];
    const float* Bg = Wg + (size_t)e*D_*FF_;
    const float* Bu = Wu + (size_t)e*D_*FF_;
    int col0 = blockIdx.x * BN;

    __shared__ float As[BK][BM+1];
    __shared__ float Bgs[BK][BN+1];
    __shared__ float Bus[BK][BN+1];
    __shared__ int toks[BM];

    int tid = threadIdx.x;
    int tx = tid & 15, ty = tid >> 4;
    if (tid < BM) toks[tid] = (row0 + tid < cnt) ? g_perm[seg + row0 + tid] : -1;
    __syncthreads();

    float accg[4][4] = {}, accu[4][4] = {};
    for (int k0 = 0; k0 < D_; k0 += BK) {
        #pragma unroll
        for (int i = 0; i < 4; i++) {
            int idx = tid + i*256;
            int m = idx >> 4, kk = idx & 15;
            int tok = toks[m];
            As[kk][m] = (tok >= 0) ? Y[(size_t)tok*D_ + k0 + kk] : 0.f;
        }
        #pragma unroll
        for (int i = 0; i < 4; i++) {
            int idx = tid + i*256;
            int kk = idx >> 6, n = idx & 63;
            int gn = col0 + n;
            size_t bi = (size_t)(k0+kk)*FF_ + gn;
            bool ok = (gn < FF_);
            Bgs[kk][n] = ok ? Bg[bi] : 0.f;
            Bus[kk][n] = ok ? Bu[bi] : 0.f;
        }
        __syncthreads();
        #pragma unroll
        for (int kk = 0; kk < BK; kk++) {
            float a[4], bg[4], bu[4];
            #pragma unroll
            for (int i = 0; i < 4; i++) a[i] = As[kk][ty*4+i];
            #pragma unroll
            for (int j = 0; j < 4; j++) { bg[j] = Bgs[kk][tx*4+j]; bu[j] = Bus[kk][tx*4+j]; }
            #pragma unroll
            for (int i = 0; i < 4; i++)
                #pragma unroll
                for (int j = 0; j < 4; j++) {
                    accg[i][j] = fmaf(a[i], bg[j], accg[i][j]);
                    accu[i][j] = fmaf(a[i], bu[j], accu[i][j]);
                }
        }
        __syncthreads();
    }
    #pragma unroll
    for (int i = 0; i < 4; i++) {
        int r = row0 + ty*4 + i;
        if (r >= cnt) continue;
        #pragma unroll
        for (int j = 0; j < 4; j++) {
            int n = col0 + tx*4 + j;
            if (n >= FF_) continue;
            float g = accg[i][j];
            float act = g / (1.f + expf(-g)) * accu[i][j];
            g_mact[(size_t)(seg + r)*FF_ + n] = act;
        }
    }
}

// MoE down GEMM: rows contiguous per expert segment.
__global__ void moe_down_k(const float* __restrict__ Wd)
{
    int e = blockIdx.z;
    int cnt = g_cnt[e];
    int row0 = blockIdx.y * BM;
    if (row0 >= cnt) return;
    int seg = g_off[e];
    const float* A = g_mact + (size_t)seg*FF_;
    const float* B = Wd + (size_t)e*FF_*D_;
    float* C = g_eo + (size_t)seg*D_;
    int col0 = blockIdx.x * BN;

    __shared__ float As[BK][BM+1];
    __shared__ float Bs[BK][BN+1];
    int tid = threadIdx.x;
    int tx = tid & 15, ty = tid >> 4;
    float acc[4][4] = {};

    for (int k0 = 0; k0 < FF_; k0 += BK) {
        #pragma unroll
        for (int i = 0; i < 4; i++) {
            int idx = tid + i*256;
            int m = idx >> 4, kk = idx & 15;
            int gr = row0 + m;
            As[kk][m] = (gr < cnt) ? A[(size_t)gr*FF_ + k0 + kk] : 0.f;
        }
        #pragma unroll
        for (int i = 0; i < 4; i++) {
            int idx = tid + i*256;
            int kk = idx >> 6, n = idx & 63;
            int gn = col0 + n;
            Bs[kk][n] = (gn < D_) ? B[(size_t)(k0+kk)*D_ + gn] : 0.f;
        }
        __syncthreads();
        #pragma unroll
        for (int kk = 0; kk < BK; kk++) {
            float a[4], b[4];
            #pragma unroll
            for (int i = 0; i < 4; i++) a[i] = As[kk][ty*4+i];
            #pragma unroll
            for (int j = 0; j < 4; j++) b[j] = Bs[kk][tx*4+j];
            #pragma unroll
            for (int i = 0; i < 4; i++)
                #pragma unroll
                for (int j = 0; j < 4; j++)
                    acc[i][j] = fmaf(a[i], b[j], acc[i][j]);
        }
        __syncthreads();
    }
    #pragma unroll
    for (int i = 0; i < 4; i++) {
        int r = row0 + ty*4 + i;
        if (r >= cnt) continue;
        #pragma unroll
        for (int j = 0; j < 4; j++) {
            int n = col0 + tx*4 + j;
            if (n >= D_) continue;
            C[(size_t)r*D_ + n] = acc[i][j];
        }
    }
}

__global__ void gsig_k(const float* __restrict__ Y, const float* __restrict__ gw)
{
    int t = blockIdx.x;
    float s = 0.f;
    for (int d = threadIdx.x; d < D_; d += 256) s += Y[(size_t)t*D_ + d] * gw[d];
    __shared__ float red[256];
    red[threadIdx.x] = s; __syncthreads();
    for (int st = 128; st > 0; st >>= 1) {
        if (threadIdx.x < st) red[threadIdx.x] += red[threadIdx.x+st];
        __syncthreads();
    }
    if (threadIdx.x == 0) g_gsig[t] = 1.f / (1.f + expf(-red[0]));
}

__global__ void silumul_k(float* __restrict__ sg, const float* __restrict__ su)
{
    int i = blockIdx.x*blockDim.x + threadIdx.x;
    if (i >= S_*SFF_) return;
    float g = sg[i];
    sg[i] = g / (1.f + expf(-g)) * su[i];
}

__global__ void final_k(float* __restrict__ out)
{
    int i = blockIdx.x*blockDim.x + threadIdx.x;
    if (i >= S_*D_) return;
    int t = i >> 11;        // / 2048
    int d = i & 2047;
    float m0 = g_ew[2*t]   * g_eo[(size_t)g_slot[2*t]  *D_ + d];
    float m1 = g_ew[2*t+1] * g_eo[(size_t)g_slot[2*t+1]*D_ + d];
    out[i] = g_hbuf[i] + m0 + m1 + g_shout[i]*g_gsig[t];
}

// ---------------- host launcher ---------------------------------------------
extern "C" void kernel_launch(void* const* d_in, const int* in_sizes, int n_in,
                              void* d_out, int out_size)
{
    const float* hidden = (const float*)d_in[0];
    const float* bias   = (const float*)d_in[1];
    const float* cosp   = (const float*)d_in[2];
    const float* sinp   = (const float*)d_in[3];
    const float* ln1w   = (const float*)d_in[4];
    const float* ln2w   = (const float*)d_in[5];
    const float* wq     = (const float*)d_in[6];
    const float* wk     = (const float*)d_in[7];
    const float* wv     = (const float*)d_in[8];
    const float* wg     = (const float*)d_in[9];
    const float* wo     = (const float*)d_in[10];
    const float* rw     = (const float*)d_in[11];
    const float* eg     = (const float*)d_in[12];
    const float* eu     = (const float*)d_in[13];
    const float* ed     = (const float*)d_in[14];
    const float* shg    = (const float*)d_in[15];
    const float* shu    = (const float*)d_in[16];
    const float* shd    = (const float*)d_in[17];
    const float* shgw   = (const float*)d_in[18];
    float* out = (float*)d_out;

    float *px, *pq, *pk, *pv, *pgl, *psc, *pctx, *ph, *py, *psg, *psu, *psh;
    cudaGetSymbolAddress((void**)&px,  g_x);
    cudaGetSymbolAddress((void**)&pq,  g_q);
    cudaGetSymbolAddress((void**)&pk,  g_k);
    cudaGetSymbolAddress((void**)&pv,  g_v);
    cudaGetSymbolAddress((void**)&pgl, g_gl);
    cudaGetSymbolAddress((void**)&psc, g_scores);
    cudaGetSymbolAddress((void**)&pctx,g_ctx);
    cudaGetSymbolAddress((void**)&ph,  g_hbuf);
    cudaGetSymbolAddress((void**)&py,  g_y);
    cudaGetSymbolAddress((void**)&psg, g_sg);
    cudaGetSymbolAddress((void**)&psu, g_su);
    cudaGetSymbolAddress((void**)&psh, g_shout);

    const float inv_sqrt_dh = 0.08838834764831845f;  // 1/sqrt(128)

    reset_k<<<1, 32>>>();

    // x = rmsnorm(hidden, ln1_w)
    rmsnorm_k<<<S_, 256>>>(hidden, ln1w, px);

    // q,k,v,gate projections
    gemm_f32<0><<<dim3(32,32), 256>>>(px, D_, 0, wq, D_, 0, pq, D_, 0, S_, D_, D_, 1.f, nullptr, 0, 0);
    gemm_f32<0><<<dim3(32,32), 256>>>(px, D_, 0, wk, D_, 0, pk, D_, 0, S_, D_, D_, 1.f, nullptr, 0, 0);
    gemm_f32<0><<<dim3(32,32), 256>>>(px, D_, 0, wv, D_, 0, pv, D_, 0, S_, D_, D_, 1.f, nullptr, 0, 0);
    gemm_f32<0><<<dim3(32,32), 256>>>(px, D_, 0, wg, D_, 0, pgl, D_, 0, S_, D_, D_, 1.f, nullptr, 0, 0);

    // RoPE on q,k
    rope_k<<<(S_*H_*64 + 255)/256, 256>>>(pq, pk, cosp, sinp);

    // scores[h] = q_h @ k_h^T / sqrt(dh) + bias   (batched over heads)
    gemm_f32<1><<<dim3(32,32,H_), 256>>>(pq, D_, (long long)DH_,
                                         pk, D_, (long long)DH_,
                                         psc, S_, (long long)S_*S_,
                                         S_, S_, DH_, inv_sqrt_dh,
                                         bias, S_, 0);
    // softmax rows
    softmax_k<<<H_*S_, 256>>>(psc, S_);

    // ctx[h] = attn_h @ v_h  (batched over heads)
    gemm_f32<0><<<dim3(2,32,H_), 256>>>(psc, S_, (long long)S_*S_,
                                        pv, D_, (long long)DH_,
                                        pctx, D_, (long long)DH_,
                                        S_, DH_, S_, 1.f, nullptr, 0, 0);
    // ctx *= sigmoid(x @ wg)
    sigmul_k<<<(S_*D_ + 255)/256, 256>>>(pctx, pgl);

    // h = hidden + ctx @ wo
    gemm_f32<0><<<dim3(32,32), 256>>>(pctx, D_, 0, wo, D_, 0, ph, D_, 0,
                                      S_, D_, D_, 1.f, hidden, D_, 0);

    // y = rmsnorm(h, ln2_w)
    rmsnorm_k<<<S_, 256>>>(ph, ln2w, py);

    // routing: logits -> softmax -> top2 -> counts
    router_k<<<S_, 256>>>(py, rw);
    offsets_k<<<1, 1>>>();
    scatter_k<<<(S_ + 255)/256, 256>>>();

    // grouped MoE: gate+up (fused silu*u), then down per expert segment
    moe_gateup_k<<<dim3(FF_/64, 32, E_), 256>>>(py, eg, eu);
    moe_down_k<<<dim3(D_/64, 32, E_), 256>>>(ed);

    // shared expert
    gsig_k<<<S_, 256>>>(py, shgw);
    gemm_f32<0><<<dim3(SFF_/64, 32), 256>>>(py, D_, 0, shg, SFF_, 0, psg, SFF_, 0,
                                            S_, SFF_, D_, 1.f, nullptr, 0, 0);
    gemm_f32<0><<<dim3(SFF_/64, 32), 256>>>(py, D_, 0, shu, SFF_, 0, psu, SFF_, 0,
                                            S_, SFF_, D_, 1.f, nullptr, 0, 0);
    silumul_k<<<(S_*SFF_ + 255)/256, 256>>>(psg, psu);
    gemm_f32<0><<<dim3(D_/64, 32), 256>>>(psg, SFF_, 0, shd, D_, 0, psh, D_, 0,
                                          S_, D_, SFF_, 1.f, nullptr, 0, 0);

    // out = h + moe + sh * sigmoid(y @ sh_gate_w)
    final_k<<<(S_*D_ + 255)/256, 256>>>(out);
}

// round 3
// speedup vs baseline: 3.6438x; 3.6438x over previous
#include <cuda_runtime.h>
#include <math.h>
#include <stdint.h>

#define S_   2048
#define D_   2048
#define H_   16
#define DH_  128
#define E_   8
#define FF_  768
#define SFF_ 4096
#define EPS_ 1e-6f

// ---------------- scratch (device globals; no allocations allowed) ----------
__device__ float g_x[S_*D_];
__device__ float g_q[S_*D_];
__device__ float g_k[S_*D_];
__device__ float g_v[S_*D_];
__device__ float g_gl[S_*D_];
__device__ float g_scores[(size_t)H_*S_*S_];   // 256 MB; reused as "up" scratch later
__device__ float g_ctx[S_*D_];
__device__ float g_hbuf[S_*D_];
__device__ float g_y[S_*D_];
__device__ float g_sg[S_*SFF_];
__device__ float g_shout[S_*D_];
__device__ float g_gsig[S_];
__device__ int   g_eidx[S_*2];
__device__ float g_ew[S_*2];
__device__ int   g_cnt[E_];
__device__ int   g_off[E_+1];
__device__ int   g_fill[E_];
__device__ int   g_perm[S_*2];
__device__ int   g_slot[S_*2];
__device__ float g_mact[(size_t)S_*2*FF_];

// ================= small PTX helpers (baseline sm_80+ features only) ========
__device__ __forceinline__ uint32_t smem_u32(const void* p) {
    uint32_t a;
    asm("{ .reg .u64 t; cvta.to.shared.u64 t, %1; cvt.u32.u64 %0, t; }" : "=r"(a) : "l"(p));
    return a;
}
__device__ __forceinline__ uint32_t f2tf(float x) {
    uint32_t r;
    asm("cvt.rna.tf32.f32 %0, %1;" : "=r"(r) : "f"(x));
    return r;
}
__device__ __forceinline__ void cpasync16(uint32_t dst, const float* src) {
    asm volatile("cp.async.cg.shared.global [%0], [%1], 16;"
        :: "r"(dst), "l"((unsigned long long)__cvta_generic_to_global(src)));
}
__device__ __forceinline__ void mma8(float c[4], const uint32_t a[4], const uint32_t b[2]) {
    asm volatile("mma.sync.aligned.m16n8k8.row.col.f32.tf32.tf32.f32 "
        "{%0,%1,%2,%3}, {%4,%5,%6,%7}, {%8,%9}, {%0,%1,%2,%3};"
        : "+f"(c[0]), "+f"(c[1]), "+f"(c[2]), "+f"(c[3])
        : "r"(a[0]), "r"(a[1]), "r"(a[2]), "r"(a[3]), "r"(b[0]), "r"(b[1]));
}

// ================= tf32 mma.sync GEMM ========================================
// C = alpha * A @ B (+ addend). Block tile 128x128, BK=32, 256 threads,
// 8 warps (4 x 2), warp tile 32x64, m16n8k8 tf32, cp.async double buffer.
// TB=0: B is [K,N] row-major (natural weight layout), smem [32][132].
// TB=1: B is [N,K] row-major (e.g. K^T for scores),  smem [128][36].
// MOE=0: dense (blockIdx.z batches via strides).
// MOE=1: A rows gathered via g_perm (expert gate/up); C rows = segment rows.
// MOE=2: A rows = segment rows (expert down);         C rows = segment rows.
template<int TB, int MOE>
__global__ __launch_bounds__(256, 1) void mma_gemm(
    const float* __restrict__ A, long long lda, long long strideA,
    const float* __restrict__ B, long long ldb, long long strideB,
    float* __restrict__ C, long long ldc, long long strideC,
    const float* __restrict__ add_, long long ldadd, long long strideAdd,
    int M, int N, int K, float alpha)
{
    int cnt = M, seg = 0;
    if (MOE) {
        int e = blockIdx.z;
        cnt = g_cnt[e]; seg = g_off[e];
        if ((int)(blockIdx.y * 128) >= cnt) return;
        B += (long long)e * strideB;
    } else {
        A += (long long)blockIdx.z * strideA;
        B += (long long)blockIdx.z * strideB;
        C += (long long)blockIdx.z * strideC;
        if (add_) add_ += (long long)blockIdx.z * strideAdd;
    }
    const int rowBase = blockIdx.y * 128;
    const int colBase = blockIdx.x * 128;

    extern __shared__ float sm[];
    float* As = sm;                         // [2][128*36]
    float* Bs = sm + 2 * 128 * 36;          // [2][BSTRIDE]
    const int BSTRIDE = TB ? 128 * 36 : 32 * 132;

    const int tid = threadIdx.x, lane = tid & 31, wid = tid >> 5;
    const int wm = wid & 3, wn = wid >> 2;

    const float* aSrc[4]; uint32_t aDst[4];
    const float* bSrc[4]; uint32_t bDst[4];
    const uint32_t sA32 = smem_u32(As), sB32 = smem_u32(Bs);
    #pragma unroll
    for (int i = 0; i < 4; i++) {
        int f = tid + i * 256;
        int row = f >> 3, c4 = f & 7;
        int r = rowBase + row;
        long long arow;
        if (MOE == 1)      { int rr = min(r, cnt - 1); arow = g_perm[seg + rr]; }
        else if (MOE == 2) { int rr = min(r, cnt - 1); arow = seg + rr; }
        else               arow = r;
        aSrc[i] = A + arow * lda + c4 * 4;
        aDst[i] = sA32 + (uint32_t)(row * 36 + c4 * 4) * 4u;
        if (TB) {
            bSrc[i] = B + (long long)(colBase + row) * ldb + c4 * 4;
            bDst[i] = sB32 + (uint32_t)(row * 36 + c4 * 4) * 4u;
        } else {
            int kk = f >> 5, c = f & 31;
            bSrc[i] = B + (long long)kk * ldb + colBase + c * 4;
            bDst[i] = sB32 + (uint32_t)(kk * 132 + c * 4) * 4u;
        }
    }

    float acc[2][8][4] = {};
    const int NC = K >> 5;

    // issue tile c into buffer c&1
    #define ISSUE(c) do { \
        int _buf = (c) & 1; \
        uint32_t _ao = (uint32_t)_buf * 128u * 36u * 4u; \
        uint32_t _bo = (uint32_t)_buf * (uint32_t)BSTRIDE * 4u; \
        _Pragma("unroll") \
        for (int _i = 0; _i < 4; _i++) { \
            cpasync16(aDst[_i] + _ao, aSrc[_i] + (long long)(c) * 32); \
            if (TB) cpasync16(bDst[_i] + _bo, bSrc[_i] + (long long)(c) * 32); \
            else    cpasync16(bDst[_i] + _bo, bSrc[_i] + (long long)(c) * 32 * ldb); \
        } \
        asm volatile("cp.async.commit_group;"); \
    } while (0)

    ISSUE(0);
    for (int c = 0; c < NC; c++) {
        if (c + 1 < NC) {
            ISSUE(c + 1);
            asm volatile("cp.async.wait_group 1;");
        } else {
            asm volatile("cp.async.wait_group 0;");
        }
        __syncthreads();
        const float* Ab = As + (c & 1) * 128 * 36;
        const float* Bb = Bs + (c & 1) * BSTRIDE;
        #pragma unroll
        for (int kk = 0; kk < 4; kk++) {
            uint32_t af[2][4];
            const int ar = wm * 32 + (lane >> 2);
            const int ac = kk * 8 + (lane & 3);
            #pragma unroll
            for (int mt = 0; mt < 2; mt++) {
                int rb = ar + mt * 16;
                af[mt][0] = f2tf(Ab[rb * 36 + ac]);
                af[mt][1] = f2tf(Ab[(rb + 8) * 36 + ac]);
                af[mt][2] = f2tf(Ab[rb * 36 + ac + 4]);
                af[mt][3] = f2tf(Ab[(rb + 8) * 36 + ac + 4]);
            }
            uint32_t bf[8][2];
            #pragma unroll
            for (int nt = 0; nt < 8; nt++) {
                int nb = wn * 64 + nt * 8 + (lane >> 2);
                if (TB) {
                    bf[nt][0] = f2tf(Bb[nb * 36 + kk * 8 + (lane & 3)]);
                    bf[nt][1] = f2tf(Bb[nb * 36 + kk * 8 + (lane & 3) + 4]);
                } else {
                    bf[nt][0] = f2tf(Bb[(kk * 8 + (lane & 3)) * 132 + nb]);
                    bf[nt][1] = f2tf(Bb[(kk * 8 + (lane & 3) + 4) * 132 + nb]);
                }
            }
            #pragma unroll
            for (int mt = 0; mt < 2; mt++)
                #pragma unroll
                for (int nt = 0; nt < 8; nt++)
                    mma8(acc[mt][nt], af[mt], bf[nt]);
        }
        __syncthreads();
    }
    #undef ISSUE

    // epilogue
    #pragma unroll
    for (int mt = 0; mt < 2; mt++) {
        const int lr0 = rowBase + wm * 32 + mt * 16 + (lane >> 2);
        const int lr1 = lr0 + 8;
        const long long cr0 = MOE ? (long long)(seg + lr0) : (long long)lr0;
        const long long cr1 = MOE ? (long long)(seg + lr1) : (long long)lr1;
        const bool ok0 = MOE ? (lr0 < cnt) : true;
        const bool ok1 = MOE ? (lr1 < cnt) : true;
        #pragma unroll
        for (int nt = 0; nt < 8; nt++) {
            const int cc = colBase + wn * 64 + nt * 8 + (lane & 3) * 2;
            if (ok0) {
                float2 v; v.x = alpha * acc[mt][nt][0]; v.y = alpha * acc[mt][nt][1];
                if (add_) {
                    float2 t = *(const float2*)&add_[(long long)lr0 * ldadd + cc];
                    v.x += t.x; v.y += t.y;
                }
                *(float2*)&C[cr0 * ldc + cc] = v;
            }
            if (ok1) {
                float2 v; v.x = alpha * acc[mt][nt][2]; v.y = alpha * acc[mt][nt][3];
                if (add_) {
                    float2 t = *(const float2*)&add_[(long long)lr1 * ldadd + cc];
                    v.x += t.x; v.y += t.y;
                }
                *(float2*)&C[cr1 * ldc + cc] = v;
            }
        }
    }
}

// ---------------- elementwise / reduction kernels ---------------------------
__global__ void reset_k() { int i = threadIdx.x; if (i < E_) g_cnt[i] = 0; }

__global__ void rmsnorm_k(const float* __restrict__ in, const float* __restrict__ w,
                          float* __restrict__ outp)
{
    int s = blockIdx.x;
    const float* x = in + (size_t)s * D_;
    float* o = outp + (size_t)s * D_;
    float ss = 0.f;
    for (int d = threadIdx.x; d < D_; d += 256) { float v = x[d]; ss += v*v; }
    __shared__ float red[256];
    red[threadIdx.x] = ss; __syncthreads();
    for (int st = 128; st > 0; st >>= 1) {
        if (threadIdx.x < st) red[threadIdx.x] += red[threadIdx.x+st];
        __syncthreads();
    }
    float r = rsqrtf(red[0]/(float)D_ + EPS_);
    for (int d = threadIdx.x; d < D_; d += 256) o[d] = x[d]*r*(1.f + w[d]);
}

__global__ void rope_k(float* __restrict__ q, float* __restrict__ k,
                       const float* __restrict__ cosp, const float* __restrict__ sinp)
{
    int idx = blockIdx.x*blockDim.x + threadIdx.x;
    if (idx >= S_*H_*64) return;
    int d = idx & 63;
    int h = (idx >> 6) & 15;
    int s = idx >> 10;
    float c1 = cosp[s*DH_ + d],      s1 = sinp[s*DH_ + d];
    float c2 = cosp[s*DH_ + d + 64], s2 = sinp[s*DH_ + d + 64];
    size_t base = (size_t)s*D_ + h*DH_ + d;
    float q1 = q[base], q2 = q[base+64];
    q[base]    = q1*c1 - q2*s1;
    q[base+64] = q2*c2 + q1*s2;
    float k1 = k[base], k2 = k[base+64];
    k[base]    = k1*c1 - k2*s1;
    k[base+64] = k2*c2 + k1*s2;
}

__global__ void softmax_k(float* __restrict__ data, int ncols)
{
    size_t row = blockIdx.x;
    float* p = data + row * (size_t)ncols;
    __shared__ float red[256];
    float m = -1e30f;
    for (int c = threadIdx.x; c < ncols; c += 256) m = fmaxf(m, p[c]);
    red[threadIdx.x] = m; __syncthreads();
    for (int st = 128; st > 0; st >>= 1) {
        if (threadIdx.x < st) red[threadIdx.x] = fmaxf(red[threadIdx.x], red[threadIdx.x+st]);
        __syncthreads();
    }
    m = red[0]; __syncthreads();
    float s = 0.f;
    for (int c = threadIdx.x; c < ncols; c += 256) { float e = expf(p[c]-m); p[c] = e; s += e; }
    red[threadIdx.x] = s; __syncthreads();
    for (int st = 128; st > 0; st >>= 1) {
        if (threadIdx.x < st) red[threadIdx.x] += red[threadIdx.x+st];
        __syncthreads();
    }
    float inv = 1.f / red[0];
    for (int c = threadIdx.x; c < ncols; c += 256) p[c] *= inv;
}

__global__ void sigmul_k(float* __restrict__ ctx, const float* __restrict__ gl)
{
    int i = blockIdx.x*blockDim.x + threadIdx.x;
    if (i >= S_*D_) return;
    ctx[i] *= 1.f / (1.f + expf(-gl[i]));
}

// a = silu(a) * b
__global__ void silumul_k(float* __restrict__ a, const float* __restrict__ b, int n)
{
    int i = blockIdx.x*blockDim.x + threadIdx.x;
    if (i >= n) return;
    float g = a[i];
    a[i] = g / (1.f + expf(-g)) * b[i];
}

__global__ void router_k(const float* __restrict__ Y, const float* __restrict__ Rw)
{
    int t = blockIdx.x;
    int tid = threadIdx.x;
    float part[E_] = {};
    for (int d = tid; d < D_; d += 256) {
        float v = Y[(size_t)t*D_ + d];
        #pragma unroll
        for (int e = 0; e < E_; e++) part[e] += v * Rw[d*E_ + e];
    }
    __shared__ float red[256];
    __shared__ float logits[E_];
    for (int e = 0; e < E_; e++) {
        red[tid] = part[e]; __syncthreads();
        for (int st = 128; st > 0; st >>= 1) {
            if (tid < st) red[tid] += red[tid+st];
            __syncthreads();
        }
        if (tid == 0) logits[e] = red[0];
        __syncthreads();
    }
    if (tid == 0) {
        float m = -1e30f;
        for (int e = 0; e < E_; e++) m = fmaxf(m, logits[e]);
        float p[E_], s = 0.f;
        for (int e = 0; e < E_; e++) { p[e] = expf(logits[e]-m); s += p[e]; }
        for (int e = 0; e < E_; e++) p[e] /= s;
        int i0 = 0;
        for (int e = 1; e < E_; e++) if (p[e] > p[i0]) i0 = e;
        int i1 = (i0 == 0) ? 1 : 0;
        for (int e = 0; e < E_; e++) if (e != i0 && p[e] > p[i1]) i1 = e;
        float sum = p[i0] + p[i1];
        g_eidx[t*2]   = i0; g_eidx[t*2+1] = i1;
        g_ew[t*2]     = p[i0]/sum;
        g_ew[t*2+1]   = p[i1]/sum;
        atomicAdd(&g_cnt[i0], 1);
        atomicAdd(&g_cnt[i1], 1);
    }
}

__global__ void offsets_k()
{
    if (threadIdx.x == 0 && blockIdx.x == 0) {
        int acc = 0;
        for (int e = 0; e < E_; e++) { g_off[e] = acc; g_fill[e] = acc; acc += g_cnt[e]; }
        g_off[E_] = acc;
    }
}

__global__ void scatter_k()
{
    int t = blockIdx.x*blockDim.x + threadIdx.x;
    if (t >= S_) return;
    #pragma unroll
    for (int k = 0; k < 2; k++) {
        int e = g_eidx[t*2+k];
        int pos = atomicAdd(&g_fill[e], 1);
        g_perm[pos] = t;
        g_slot[t*2+k] = pos;
    }
}

__global__ void gsig_k(const float* __restrict__ Y, const float* __restrict__ gw)
{
    int t = blockIdx.x;
    float s = 0.f;
    for (int d = threadIdx.x; d < D_; d += 256) s += Y[(size_t)t*D_ + d] * gw[d];
    __shared__ float red[256];
    red[threadIdx.x] = s; __syncthreads();
    for (int st = 128; st > 0; st >>= 1) {
        if (threadIdx.x < st) red[threadIdx.x] += red[threadIdx.x+st];
        __syncthreads();
    }
    if (threadIdx.x == 0) g_gsig[t] = 1.f / (1.f + expf(-red[0]));
}

// expert outputs (stored in g_ctx-reuse buffer) combined with residual+shared
__device__ float g_eo[(size_t)S_*2*D_];
__global__ void final_k(float* __restrict__ out)
{
    int i = blockIdx.x*blockDim.x + threadIdx.x;
    if (i >= S_*D_) return;
    int t = i >> 11;
    int d = i & 2047;
    float m0 = g_ew[2*t]   * g_eo[(size_t)g_slot[2*t]  *D_ + d];
    float m1 = g_ew[2*t+1] * g_eo[(size_t)g_slot[2*t+1]*D_ + d];
    out[i] = g_hbuf[i] + m0 + m1 + g_shout[i]*g_gsig[t];
}

// ---------------- host launcher ---------------------------------------------
extern "C" void kernel_launch(void* const* d_in, const int* in_sizes, int n_in,
                              void* d_out, int out_size)
{
    const float* hidden = (const float*)d_in[0];
    const float* bias   = (const float*)d_in[1];
    const float* cosp   = (const float*)d_in[2];
    const float* sinp   = (const float*)d_in[3];
    const float* ln1w   = (const float*)d_in[4];
    const float* ln2w   = (const float*)d_in[5];
    const float* wq     = (const float*)d_in[6];
    const float* wk     = (const float*)d_in[7];
    const float* wv     = (const float*)d_in[8];
    const float* wg     = (const float*)d_in[9];
    const float* wo     = (const float*)d_in[10];
    const float* rw     = (const float*)d_in[11];
    const float* eg     = (const float*)d_in[12];
    const float* eu     = (const float*)d_in[13];
    const float* ed     = (const float*)d_in[14];
    const float* shg    = (const float*)d_in[15];
    const float* shu    = (const float*)d_in[16];
    const float* shd    = (const float*)d_in[17];
    const float* shgw   = (const float*)d_in[18];
    float* out = (float*)d_out;

    float *px, *pq, *pk, *pv, *pgl, *psc, *pctx, *ph, *py, *psg, *psh, *pmact, *peo;
    cudaGetSymbolAddress((void**)&px,  g_x);
    cudaGetSymbolAddress((void**)&pq,  g_q);
    cudaGetSymbolAddress((void**)&pk,  g_k);
    cudaGetSymbolAddress((void**)&pv,  g_v);
    cudaGetSymbolAddress((void**)&pgl, g_gl);
    cudaGetSymbolAddress((void**)&psc, g_scores);
    cudaGetSymbolAddress((void**)&pctx,g_ctx);
    cudaGetSymbolAddress((void**)&ph,  g_hbuf);
    cudaGetSymbolAddress((void**)&py,  g_y);
    cudaGetSymbolAddress((void**)&psg, g_sg);
    cudaGetSymbolAddress((void**)&psh, g_shout);
    cudaGetSymbolAddress((void**)&pmact, g_mact);
    cudaGetSymbolAddress((void**)&peo, g_eo);

    const int SM_TB0 = (2*128*36 + 2*32*132) * 4;   // 70656
    const int SM_TB1 = (2*128*36 + 2*128*36) * 4;   // 73728
    cudaFuncSetAttribute(mma_gemm<0,0>, cudaFuncAttributeMaxDynamicSharedMemorySize, SM_TB0);
    cudaFuncSetAttribute(mma_gemm<1,0>, cudaFuncAttributeMaxDynamicSharedMemorySize, SM_TB1);
    cudaFuncSetAttribute(mma_gemm<0,1>, cudaFuncAttributeMaxDynamicSharedMemorySize, SM_TB0);
    cudaFuncSetAttribute(mma_gemm<0,2>, cudaFuncAttributeMaxDynamicSharedMemorySize, SM_TB0);

    const float isd = 0.08838834764831845f;   // 1/sqrt(128)

    reset_k<<<1, 32>>>();
    rmsnorm_k<<<S_, 256>>>(hidden, ln1w, px);

    // q,k,v,gate projections: x[S,D] @ W[D,N] (natural layout, TB=0)
    mma_gemm<0,0><<<dim3(16,16), 256, SM_TB0>>>(px, D_, 0, wq, D_, 0, pq, D_, 0, nullptr, 0, 0, S_, D_, D_, 1.f);
    mma_gemm<0,0><<<dim3(16,16), 256, SM_TB0>>>(px, D_, 0, wk, D_, 0, pk, D_, 0, nullptr, 0, 0, S_, D_, D_, 1.f);
    mma_gemm<0,0><<<dim3(16,16), 256, SM_TB0>>>(px, D_, 0, wv, D_, 0, pv, D_, 0, nullptr, 0, 0, S_, D_, D_, 1.f);
    mma_gemm<0,0><<<dim3(16,16), 256, SM_TB0>>>(px, D_, 0, wg, D_, 0, pgl, D_, 0, nullptr, 0, 0, S_, D_, D_, 1.f);

    rope_k<<<(S_*H_*64 + 255)/256, 256>>>(pq, pk, cosp, sinp);

    // scores[h] = (q_h @ k_h^T) * isd + bias  (B=[N,K] => TB=1), batched over heads
    mma_gemm<1,0><<<dim3(16,16,H_), 256, SM_TB1>>>(pq, D_, DH_,
                                                   pk, D_, DH_,
                                                   psc, S_, (long long)S_*S_,
                                                   bias, S_, 0,
                                                   S_, S_, DH_, isd);
    softmax_k<<<H_*S_, 256>>>(psc, S_);

    // ctx[h] = attn_h @ v_h  (B=v in [K,N] form, TB=0)
    mma_gemm<0,0><<<dim3(1,16,H_), 256, SM_TB0>>>(psc, S_, (long long)S_*S_,
                                                  pv, D_, DH_,
                                                  pctx, D_, DH_,
                                                  nullptr, 0, 0,
                                                  S_, DH_, S_, 1.f);
    sigmul_k<<<(S_*D_ + 255)/256, 256>>>(pctx, pgl);

    // h = hidden + ctx @ wo
    mma_gemm<0,0><<<dim3(16,16), 256, SM_TB0>>>(pctx, D_, 0, wo, D_, 0, ph, D_, 0,
                                                hidden, D_, 0, S_, D_, D_, 1.f);

    rmsnorm_k<<<S_, 256>>>(ph, ln2w, py);
    router_k<<<S_, 256>>>(py, rw);
    offsets_k<<<1, 1>>>();
    scatter_k<<<(S_ + 255)/256, 256>>>();

    // shared expert: gate -> g_sg, up -> g_scores (reused), silu*up, down -> g_shout
    mma_gemm<0,0><<<dim3(32,16), 256, SM_TB0>>>(py, D_, 0, shg, SFF_, 0, psg, SFF_, 0,
                                                nullptr, 0, 0, S_, SFF_, D_, 1.f);
    mma_gemm<0,0><<<dim3(32,16), 256, SM_TB0>>>(py, D_, 0, shu, SFF_, 0, psc, SFF_, 0,
                                                nullptr, 0, 0, S_, SFF_, D_, 1.f);
    silumul_k<<<(S_*SFF_ + 255)/256, 256>>>(psg, psc, S_*SFF_);
    mma_gemm<0,0><<<dim3(16,16), 256, SM_TB0>>>(psg, SFF_, 0, shd, D_, 0, psh, D_, 0,
                                                nullptr, 0, 0, S_, D_, SFF_, 1.f);
    gsig_k<<<S_, 256>>>(py, shgw);

    // MoE experts (grouped): gate -> g_mact, up -> g_scores (reused), silu*up, down -> g_eo
    mma_gemm<0,1><<<dim3(FF_/128, 16, E_), 256, SM_TB0>>>(py, D_, 0, eg, FF_, (long long)D_*FF_,
                                                          pmact, FF_, 0, nullptr, 0, 0,
                                                          0, FF_, D_, 1.f);
    mma_gemm<0,1><<<dim3(FF_/128, 16, E_), 256, SM_TB0>>>(py, D_, 0, eu, FF_, (long long)D_*FF_,
                                                          psc, FF_, 0, nullptr, 0, 0,
                                                          0, FF_, D_, 1.f);
    silumul_k<<<(S_*2*FF_ + 255)/256, 256>>>(pmact, psc, S_*2*FF_);
    mma_gemm<0,2><<<dim3(16, 16, E_), 256, SM_TB0>>>(pmact, FF_, 0, ed, D_, (long long)FF_*D_,
                                                     peo, D_, 0, nullptr, 0, 0,
                                                     0, D_, FF_, 1.f);

    final_k<<<(S_*D_ + 255)/256, 256>>>(out);
}